// round 16
// baseline (speedup 1.0000x reference)
#include <cuda_runtime.h>
#include <cuda_fp16.h>
#include <cstdint>
#include <math.h>

#define BB 32
#define NN 1024
#define HH 256
#define AA 32
#define OO 256
#define MM (BB*NN)   // 32768 particle rows

// ---------------- scratch (static device arrays; no allocation) -------------
__device__ float g_NXT[MM*HH];
__device__ float g_ll[MM];
__device__ int   g_idx[MM];
__device__ float g_partial[BB*128*HH];

__device__ __align__(128) __half g_U16[MM*HH];
__device__ __align__(128) __half g_ACT[BB*AA];
__device__ __align__(128) __half g_OBS[BB*OO];

// transposed fp16 weights [n][k]: Wr | Wu | Wc | W0 | W1
#define WT_TOTAL 417792
__device__ __align__(128) __half g_WT[WT_TOTAL];
// offsets: Wr 0, Wu 73728, Wc 147456, W0 221184, W1 352256

__device__ __forceinline__ float fast_sigmoid(float x){
    return __fdividef(1.f, 1.f + __expf(-x));
}
__device__ __forceinline__ float fast_tanh(float x){
    float r; asm("tanh.approx.f32 %0, %1;" : "=f"(r) : "f"(x)); return r;
}
__device__ __forceinline__ float gelu_f(float x){ return 0.5f*x*(1.0f+erff(x*0.70710678118654752f)); }
__device__ __forceinline__ float gelu_fast(float x){
    const float c = 0.7978845608028654f;
    return 0.5f*x*(1.0f + fast_tanh(c*(x + 0.044715f*x*x*x)));
}

__device__ __forceinline__ uint32_t packh(float x, float y){
    __half hx = __float2half_rn(x), hy = __float2half_rn(y);
    return (uint32_t)__half_as_ushort(hx) | ((uint32_t)__half_as_ushort(hy) << 16);
}
__device__ __forceinline__ float2 unpackh(uint32_t v){
    __half lo = __ushort_as_half((unsigned short)(v & 0xffff));
    __half hi = __ushort_as_half((unsigned short)(v >> 16));
    return make_float2(__half2float(lo), __half2float(hi));
}

__device__ __forceinline__ void mma16816(float* c, const uint32_t* a, uint32_t b0, uint32_t b1){
    asm volatile("mma.sync.aligned.m16n8k16.row.col.f32.f16.f16.f32 "
        "{%0,%1,%2,%3}, {%4,%5,%6,%7}, {%8,%9}, {%0,%1,%2,%3};"
        : "+f"(c[0]), "+f"(c[1]), "+f"(c[2]), "+f"(c[3])
        : "r"(a[0]), "r"(a[1]), "r"(a[2]), "r"(a[3]), "r"(b0), "r"(b1));
}
__device__ __forceinline__ uint32_t smem_u32(const void* p){
    uint32_t a;
    asm("{ .reg .u64 t; cvta.to.shared.u64 t, %1; cvt.u32.u64 %0, t; }" : "=r"(a) : "l"(p));
    return a;
}

#define CP16(dst, src) \
    asm volatile("cp.async.cg.shared.global [%0], [%1], 16;" :: "r"(dst), "l"(src) : "memory")
#define CP_COMMIT() asm volatile("cp.async.commit_group;" ::: "memory")
#define CP_WAITN(n) asm volatile("cp.async.wait_group %0;" :: "n"(n) : "memory")
#define LDM4(r0,r1,r2,r3,addr) \
    asm volatile("ldmatrix.sync.aligned.m8n8.x4.shared.b16 {%0,%1,%2,%3}, [%4];" \
        : "=r"(r0),"=r"(r1),"=r"(r2),"=r"(r3) : "r"(addr))

// smem layout: single in-place A region + 6-slot W ring
#define PITCH_A 528
#define WPITCH 80
#define WPANEL (256*WPITCH)     // 20480
#define NSLOT 6
#define OFF_A   0               // 128*528 = 67584
#define OFF_W   67584           // 6*20480 = 122880 -> ends 190464
#define OFF_ACT 190464
#define OFF_OBS 190528
#define OFF_RED 191040
#define SMEM_TOTAL 193152

// ---------------------------------------------------------------------------
// Prep: weights transpose+convert (z=0..4) and act/obs convert (z=5)
// ---------------------------------------------------------------------------
__global__ void wprep_k(const float* __restrict__ Wr, const float* __restrict__ Wu,
                        const float* __restrict__ Wc, const float* __restrict__ W0,
                        const float* __restrict__ W1,
                        const float* __restrict__ act, const float* __restrict__ obs)
{
    const int mid = blockIdx.z;
    const int tx = threadIdx.x, ty = threadIdx.y;
    if (mid == 5){
        if (blockIdx.x == 0 && blockIdx.y == 0){
            const int t = ty*32 + tx;
            for (int i = t; i < BB*AA; i += 256)
                g_ACT[i] = __float2half_rn(act[i]);
            for (int i = t; i < BB*OO; i += 256)
                g_OBS[i] = __float2half_rn(obs[i]);
        }
        return;
    }
    const int Ks[5] = {288,288,288,512,256};
    const size_t offs[5] = {0,73728,147456,221184,352256};
    const float* src = (mid==0)?Wr:(mid==1)?Wu:(mid==2)?Wc:(mid==3)?W0:W1;
    const int K = Ks[mid];
    const int k0 = blockIdx.x * 32;
    if (k0 >= K) return;
    const int n0 = blockIdx.y * 32;

    __shared__ float tile[32][33];
#pragma unroll
    for (int i=0;i<4;i++)
        tile[ty*4+i][tx] = src[(size_t)(k0+ty*4+i)*HH + n0 + tx];
    __syncthreads();
#pragma unroll
    for (int i=0;i<4;i++){
        const int r = ty*4+i;
        g_WT[offs[mid] + (size_t)(n0+r)*K + k0 + tx] = __float2half_rn(tile[tx][r]);
    }
}

// ---------------------------------------------------------------------------
__device__ __forceinline__ void stage_w(uint32_t buf, const __half* __restrict__ w,
                                        int KP, int k0, int tid)
{
#pragma unroll
    for (int i=0;i<2;i++){
        const int idx = tid + i*512;
        const int row = idx >> 2, seg = idx & 3;
        CP16(buf + (uint32_t)(row*WPITCH + seg*16), w + (size_t)row*KP + k0 + seg*8);
    }
}

// prestage the first 4 panels of a phase (overlap with preceding epilogue)
__device__ __forceinline__ void prestage4(uint32_t wring, const __half* __restrict__ w,
                                          int KP, int base, int tid)
{
#pragma unroll
    for (int j=0;j<4;j++){
        stage_w(wring + ((base + j) % NSLOT)*WPANEL, w, KP, j*32, tid);
        CP_COMMIT();
    }
}

// ---------------------------------------------------------------------------
// One GEMM phase: panels 0..3 pre-staged at slots base..base+3.
// Per panel: wait (panel p done) -> barrier -> stage p+4 -> compute.
// ---------------------------------------------------------------------------
template<int Kc>
__device__ __forceinline__ void gemm_phase(
    uint32_t aBase, uint32_t bcBase, uint32_t wring,
    const __half* __restrict__ w, int KP,
    int tid, int warpM, int warpN, int t8, int r8,
    float acc[2][8][4], int base)
{
    constexpr int P = Kc / 32;
#pragma unroll
    for (int i=0;i<2;i++)
#pragma unroll
        for (int j=0;j<8;j++)
#pragma unroll
            for (int q=0;q<4;q++) acc[i][j][q] = 0.f;

#pragma unroll 1
    for (int p = 0; p < P; ++p){
        const int wg = (P-1-p < 3) ? (P-1-p) : 3;
        switch (wg){
            case 3: CP_WAITN(3); break;
            case 2: CP_WAITN(2); break;
            case 1: CP_WAITN(1); break;
            default: CP_WAITN(0); break;
        }
        __syncthreads();   // all threads' panel-p portions visible; write-slot WAR

        if (p + 4 < P){
            stage_w(wring + ((base + p + 4) % NSLOT)*WPANEL, w, KP, (p+4)*32, tid);
            CP_COMMIT();
        }

        const uint32_t bS = wring + ((base + p) % NSLOT)*WPANEL;

        uint32_t ahA[2][2][4];
#pragma unroll
        for (int ks = 0; ks < 2; ++ks){
            const int kk = p*32 + ks*16;
            if (kk < 256){
#pragma unroll
                for (int mf = 0; mf < 2; ++mf){
                    const uint32_t off = (uint32_t)((warpM*32 + mf*16 + (t8&1)*8 + r8)*PITCH_A
                                                    + (t8>>1)*16 + kk*2);
                    LDM4(ahA[ks][mf][0],ahA[ks][mf][1],ahA[ks][mf][2],ahA[ks][mf][3], aBase + off);
                }
            } else {
                const uint32_t off = bcBase + (uint32_t)((kk-256)*2 + (t8>>1)*16);
                LDM4(ahA[ks][0][0],ahA[ks][0][1],ahA[ks][0][2],ahA[ks][0][3], off);
                ahA[ks][1][0]=ahA[ks][0][0]; ahA[ks][1][1]=ahA[ks][0][1];
                ahA[ks][1][2]=ahA[ks][0][2]; ahA[ks][1][3]=ahA[ks][0][3];
            }
        }

#pragma unroll
        for (int ks = 0; ks < 2; ++ks){
#pragma unroll
            for (int q = 0; q < 4; ++q){
                const uint32_t boff = (uint32_t)((warpN*64 + q*16 + (t8>>1)*8 + r8)*WPITCH
                                                 + (t8&1)*16 + ks*32);
                uint32_t b0_,b1_,b2_,b3_;
                LDM4(b0_,b1_,b2_,b3_, bS + boff);
                mma16816(acc[0][2*q],   ahA[ks][0], b0_, b1_);
                mma16816(acc[1][2*q],   ahA[ks][1], b0_, b1_);
                mma16816(acc[0][2*q+1], ahA[ks][0], b2_, b3_);
                mma16816(acc[1][2*q+1], ahA[ks][1], b2_, b3_);
            }
        }
    }
}

// ---------------------------------------------------------------------------
// Fused chain (in-place A): G1b(Wu->U) G1a(Wr->XR) G2(Wc->nxt) G3(W0->Z1) G4(W1->ll)
// panel counts 9,9,9,16,8 -> phase base slots 0,3,0,3,1 (cumulative mod 6)
// ---------------------------------------------------------------------------
__global__ void __launch_bounds__(512, 1) fused_k(
    const float* __restrict__ particles,
    const float* __restrict__ br, const float* __restrict__ bu,
    const float* __restrict__ bc, const float* __restrict__ b0,
    const float* __restrict__ b1, const float* __restrict__ W2)
{
    extern __shared__ __align__(128) char smem[];
    const uint32_t sb = smem_u32(smem);

    const int tid  = threadIdx.x;
    const int wid  = tid >> 5;
    const int lane = tid & 31;
    const int g    = lane >> 2;
    const int tig  = lane & 3;
    const int t8   = lane >> 3;
    const int r8   = lane & 7;
    const int warpM = wid >> 2;
    const int warpN = wid & 3;
    const int m0   = blockIdx.x * 128;
    const int bidx = blockIdx.x >> 3;

    // ---- prologue ----
    if (tid < 4)  CP16(sb + OFF_ACT + tid*16, g_ACT + bidx*AA + tid*8);
    if (tid < 32) CP16(sb + OFF_OBS + tid*16, g_OBS + bidx*OO + tid*8);
    CP_COMMIT();
    prestage4(sb+OFF_W, g_WT+73728, 288, 0, tid);   // G1b (Wu) panels 0..3
#pragma unroll
    for (int i=0;i<8;i++){
        const int idx = tid + i*512;
        const int row = idx >> 5, seg = idx & 31;
        const float4 v0 = *(const float4*)(particles + (size_t)(m0+row)*HH + seg*8);
        const float4 v1 = *(const float4*)(particles + (size_t)(m0+row)*HH + seg*8 + 4);
        uint4 pk;
        pk.x = packh(v0.x, v0.y); pk.y = packh(v0.z, v0.w);
        pk.z = packh(v1.x, v1.y); pk.w = packh(v1.z, v1.w);
        *(uint4*)(smem + OFF_A + row*PITCH_A + seg*16) = pk;
    }
    __syncthreads();

    float acc[2][8][4];

    // =============== G1b: update gate -> g_U16 (A untouched) ===============
    gemm_phase<288>(sb+OFF_A, sb+OFF_ACT, sb+OFF_W, g_WT+73728, 288,
                    tid, warpM, warpN, t8, r8, acc, 0);
    __syncthreads();
    prestage4(sb+OFF_W, g_WT, 288, 3, tid);         // G1a (Wr) prefetch
#pragma unroll
    for (int mf=0; mf<2; ++mf){
#pragma unroll
        for (int nf=0; nf<8; ++nf){
            const int nc = warpN*64 + nf*8 + tig*2;
            const int m1_ = m0 + warpM*32 + mf*16 + g;
            const int m2_ = m1_ + 8;
            const float2 bv = *(const float2*)(bu + nc);
            float* c = acc[mf][nf];
            *(uint32_t*)&g_U16[(size_t)m1_*HH+nc] = packh(fast_sigmoid(c[0]+bv.x), fast_sigmoid(c[1]+bv.y));
            *(uint32_t*)&g_U16[(size_t)m2_*HH+nc] = packh(fast_sigmoid(c[2]+bv.x), fast_sigmoid(c[3]+bv.y));
        }
    }
    __syncthreads();

    // =============== G1a: reset gate -> XR (in-place A) ===============
    gemm_phase<288>(sb+OFF_A, sb+OFF_ACT, sb+OFF_W, g_WT, 288,
                    tid, warpM, warpN, t8, r8, acc, 3);
    __syncthreads();                                  // A reads done
    prestage4(sb+OFF_W, g_WT+147456, 288, 0, tid);  // G2 (Wc) prefetch
#pragma unroll
    for (int mf=0; mf<2; ++mf){
#pragma unroll
        for (int nf=0; nf<8; ++nf){
            const int nc = warpN*64 + nf*8 + tig*2;
            const int mm1 = warpM*32 + mf*16 + g;
            const int mm2 = mm1 + 8;
            const float2 bv = *(const float2*)(br + nc);
            float* c = acc[mf][nf];
            uint32_t* a1 = (uint32_t*)(smem + OFF_A + mm1*PITCH_A + nc*2);
            uint32_t* a2 = (uint32_t*)(smem + OFF_A + mm2*PITCH_A + nc*2);
            const float2 p1 = unpackh(*a1);
            const float2 p2 = unpackh(*a2);
            *a1 = packh(p1.x*fast_sigmoid(c[0]+bv.x), p1.y*fast_sigmoid(c[1]+bv.y));
            *a2 = packh(p2.x*fast_sigmoid(c[2]+bv.x), p2.y*fast_sigmoid(c[3]+bv.y));
        }
    }
    __syncthreads();

    // =============== G2: candidate + GRU combine -> nxt (in-place A) ===============
    gemm_phase<288>(sb+OFF_A, sb+OFF_ACT, sb+OFF_W, g_WT+147456, 288,
                    tid, warpM, warpN, t8, r8, acc, 0);
    __syncthreads();
    prestage4(sb+OFF_W, g_WT+221184, 512, 3, tid);  // G3 (W0) prefetch
#pragma unroll
    for (int mf=0; mf<2; ++mf){
#pragma unroll
        for (int nf=0; nf<8; ++nf){
            const int nc = warpN*64 + nf*8 + tig*2;
            const int mm1 = warpM*32 + mf*16 + g;
            const int mm2 = mm1 + 8;
            const int m1_ = m0 + mm1, m2_ = m0 + mm2;
            const float2 bv = *(const float2*)(bc + nc);
            float* c = acc[mf][nf];
            const float2 u1 = unpackh(*(uint32_t*)&g_U16[(size_t)m1_*HH+nc]);
            const float2 u2 = unpackh(*(uint32_t*)&g_U16[(size_t)m2_*HH+nc]);
            const float2 p1 = *(const float2*)(particles + (size_t)m1_*HH + nc);
            const float2 p2 = *(const float2*)(particles + (size_t)m2_*HH + nc);
            float2 r1, r2;
            r1.x = (1.f-u1.x)*p1.x + u1.x*fast_tanh(c[0]+bv.x);
            r1.y = (1.f-u1.y)*p1.y + u1.y*fast_tanh(c[1]+bv.y);
            r2.x = (1.f-u2.x)*p2.x + u2.x*fast_tanh(c[2]+bv.x);
            r2.y = (1.f-u2.y)*p2.y + u2.y*fast_tanh(c[3]+bv.y);
            *(float2*)(g_NXT + (size_t)m1_*HH + nc) = r1;
            *(float2*)(g_NXT + (size_t)m2_*HH + nc) = r2;
            *(uint32_t*)(smem + OFF_A + mm1*PITCH_A + nc*2) = packh(r1.x, r1.y);
            *(uint32_t*)(smem + OFF_A + mm2*PITCH_A + nc*2) = packh(r2.x, r2.y);
        }
    }
    __syncthreads();

    // =============== G3: MLP layer 0 -> Z1 (in-place A, fast gelu) ===============
    gemm_phase<512>(sb+OFF_A, sb+OFF_OBS, sb+OFF_W, g_WT+221184, 512,
                    tid, warpM, warpN, t8, r8, acc, 3);
    __syncthreads();
    prestage4(sb+OFF_W, g_WT+352256, 256, 1, tid);  // G4 (W1) prefetch
#pragma unroll
    for (int mf=0; mf<2; ++mf){
#pragma unroll
        for (int nf=0; nf<8; ++nf){
            const int nc = warpN*64 + nf*8 + tig*2;
            const int mm1 = warpM*32 + mf*16 + g;
            const int mm2 = mm1 + 8;
            const float2 bv = *(const float2*)(b0 + nc);
            float* c = acc[mf][nf];
            *(uint32_t*)(smem + OFF_A + mm1*PITCH_A + nc*2) =
                packh(gelu_fast(c[0]+bv.x), gelu_fast(c[1]+bv.y));
            *(uint32_t*)(smem + OFF_A + mm2*PITCH_A + nc*2) =
                packh(gelu_fast(c[2]+bv.x), gelu_fast(c[3]+bv.y));
        }
    }
    __syncthreads();

    // =============== G4: MLP layer 1 + W2 dot -> log_lik (exact gelu) ===============
    gemm_phase<256>(sb+OFF_A, sb+OFF_OBS, sb+OFF_W, g_WT+352256, 256,
                    tid, warpM, warpN, t8, r8, acc, 1);
    {
        float* red = (float*)(smem + OFF_RED);
        float pr[2][2] = {{0.f,0.f},{0.f,0.f}};
#pragma unroll
        for (int mf=0; mf<2; ++mf){
#pragma unroll
            for (int nf=0; nf<8; ++nf){
                const int nc = warpN*64 + nf*8 + tig*2;
                const float2 bv = *(const float2*)(b1 + nc);
                const float2 wv = *(const float2*)(W2 + nc);
                float* c = acc[mf][nf];
                pr[mf][0] += gelu_f(c[0]+bv.x)*wv.x + gelu_f(c[1]+bv.y)*wv.y;
                pr[mf][1] += gelu_f(c[2]+bv.x)*wv.x + gelu_f(c[3]+bv.y)*wv.y;
            }
        }
        __syncthreads();
#pragma unroll
        for (int mf=0; mf<2; ++mf)
#pragma unroll
            for (int rr=0; rr<2; ++rr){
                float v = pr[mf][rr];
                v += __shfl_xor_sync(0xffffffffu, v, 1);
                v += __shfl_xor_sync(0xffffffffu, v, 2);
                if (tig == 0) red[(warpM*32 + mf*16 + rr*8 + g)*4 + warpN] = v;
            }
        __syncthreads();
        if (tid < 128)
            g_ll[m0 + tid] = red[tid*4] + red[tid*4+1] + red[tid*4+2] + red[tid*4+3];
    }
}

// ---------------------------------------------------------------------------
// Per-batch weight update: shuffle-based softmax / ESS / scan / resample idx.
// ---------------------------------------------------------------------------
__global__ void __launch_bounds__(NN) stage_weights_k(
    const float* __restrict__ weights,
    const float* __restrict__ uin,
    const float* __restrict__ b2,
    float* __restrict__ dout)
{
    __shared__ float sh[NN];
    __shared__ float swarp[32];
    __shared__ float sbc;
    const int b = blockIdx.x;
    const int n = threadIdx.x;
    const int m = b*NN + n;
    const int w = n >> 5, l = n & 31;

    const float ll = g_ll[m] + b2[0];
    const float lw = __logf(weights[m] + 1e-10f) + ll;

    float v = lw;
#pragma unroll
    for (int o=16;o>0;o>>=1) v = fmaxf(v, __shfl_xor_sync(0xffffffffu, v, o));
    if (l==0) swarp[w] = v;
    __syncthreads();
    if (w==0){
        float x = swarp[l];
#pragma unroll
        for (int o=16;o>0;o>>=1) x = fmaxf(x, __shfl_xor_sync(0xffffffffu, x, o));
        if (l==0) sbc = x;
    }
    __syncthreads();
    const float mx = sbc;
    __syncthreads();

    const float e = __expf(lw - mx);
    v = e;
#pragma unroll
    for (int o=16;o>0;o>>=1) v += __shfl_xor_sync(0xffffffffu, v, o);
    if (l==0) swarp[w] = v;
    __syncthreads();
    if (w==0){
        float x = swarp[l];
#pragma unroll
        for (int o=16;o>0;o>>=1) x += __shfl_xor_sync(0xffffffffu, x, o);
        if (l==0) sbc = x;
    }
    __syncthreads();
    const float S = sbc;
    __syncthreads();
    const float nw = __fdividef(e, S);

    v = nw*nw;
#pragma unroll
    for (int o=16;o>0;o>>=1) v += __shfl_xor_sync(0xffffffffu, v, o);
    if (l==0) swarp[w] = v;
    __syncthreads();
    if (w==0){
        float x = swarp[l];
#pragma unroll
        for (int o=16;o>0;o>>=1) x += __shfl_xor_sync(0xffffffffu, x, o);
        if (l==0) sbc = x;
    }
    __syncthreads();
    const float ess = __fdividef(1.0f, sbc + 1e-10f);
    __syncthreads();
    const bool should = ess < 0.5f * (float)NN;

    float sc = nw;
#pragma unroll
    for (int o=1;o<32;o<<=1){
        float t = __shfl_up_sync(0xffffffffu, sc, o);
        if (l >= o) sc += t;
    }
    if (l==31) swarp[w] = sc;
    __syncthreads();
    if (w==0){
        float t = swarp[l];
        float ts = t;
#pragma unroll
        for (int o=1;o<32;o<<=1){
            float u2 = __shfl_up_sync(0xffffffffu, ts, o);
            if (l >= o) ts += u2;
        }
        swarp[l] = ts - t;
    }
    __syncthreads();
    sc += swarp[w];
    sh[n] = sc;
    __syncthreads();

    float pos = uin[b]*(1.0f/(float)NN) + (float)n*(1.0f/(float)NN);
    pos = fminf(pos, 0.9999f);
    int lo = 0, hi = NN;
    while (lo < hi) {
        int mid = (lo + hi) >> 1;
        if (sh[mid] < pos) lo = mid + 1; else hi = mid;
    }
    int idx = lo < (NN-1) ? lo : (NN-1);

    g_idx[m] = should ? idx : n;
    const float wf = should ? (1.0f/(float)NN) : nw;
    dout[8192 + (size_t)MM*HH + m] = wf;
    if (n == 0) dout[8192 + (size_t)MM*HH + MM + b] = ess;
}

// ---------------------------------------------------------------------------
__global__ void __launch_bounds__(256) gather_belief_k(float* __restrict__ dout)
{
    __shared__ float4 sbuf[256];
    const int b = blockIdx.y;
    const int chunk = blockIdx.x;
    const int h4  = (threadIdx.x & 63) * 4;
    const int rg  = threadIdx.x >> 6;
    const float* dw = dout + 8192 + (size_t)MM*HH;
    float* dnxt = dout + 8192;

    float4 acc = make_float4(0.f,0.f,0.f,0.f);
#pragma unroll
    for (int r=0; r<2; r++) {
        const int j = chunk*8 + rg*2 + r;
        const int src = g_idx[b*NN + j];
        const float wj = dw[b*NN + j];
        const float4 v = *(const float4*)(g_NXT + (size_t)(b*NN + src)*HH + h4);
        *(float4*)(dnxt + (size_t)(b*NN + j)*HH + h4) = v;
        acc.x = fmaf(v.x, wj, acc.x);
        acc.y = fmaf(v.y, wj, acc.y);
        acc.z = fmaf(v.z, wj, acc.z);
        acc.w = fmaf(v.w, wj, acc.w);
    }
    sbuf[threadIdx.x] = acc;
    __syncthreads();
    if (threadIdx.x < 64){
        float4 a0 = sbuf[threadIdx.x];
        float4 a1 = sbuf[threadIdx.x + 64];
        float4 a2 = sbuf[threadIdx.x + 128];
        float4 a3 = sbuf[threadIdx.x + 192];
        float4 s;
        s.x = (a0.x + a1.x) + (a2.x + a3.x);
        s.y = (a0.y + a1.y) + (a2.y + a3.y);
        s.z = (a0.z + a1.z) + (a2.z + a3.z);
        s.w = (a0.w + a1.w) + (a2.w + a3.w);
        *(float4*)(g_partial + (size_t)(b*128 + chunk)*HH + h4) = s;
    }
}

__global__ void __launch_bounds__(64) belief_reduce_k(float* __restrict__ dout)
{
    const int b = blockIdx.x;
    const int h4 = threadIdx.x * 4;
    float4 s = make_float4(0.f,0.f,0.f,0.f);
    for (int c=0; c<128; c++){
        const float4 v = *(const float4*)(g_partial + (size_t)(b*128 + c)*HH + h4);
        s.x += v.x; s.y += v.y; s.z += v.z; s.w += v.w;
    }
    *(float4*)(dout + b*HH + h4) = s;
}

// ---------------------------------------------------------------------------
extern "C" void kernel_launch(void* const* d_in, const int* in_sizes, int n_in,
                              void* d_out, int out_size)
{
    (void)in_sizes; (void)n_in; (void)out_size;
    const float* particles   = (const float*)d_in[0];
    const float* weights     = (const float*)d_in[1];
    const float* action      = (const float*)d_in[2];
    const float* observation = (const float*)d_in[3];
    const float* uin         = (const float*)d_in[4];
    const float* Wr = (const float*)d_in[5];  const float* br = (const float*)d_in[6];
    const float* Wu = (const float*)d_in[7];  const float* bu = (const float*)d_in[8];
    const float* Wc = (const float*)d_in[9];  const float* bc = (const float*)d_in[10];
    const float* W0 = (const float*)d_in[11]; const float* b0 = (const float*)d_in[12];
    const float* W1 = (const float*)d_in[13]; const float* b1 = (const float*)d_in[14];
    const float* W2 = (const float*)d_in[15]; const float* b2 = (const float*)d_in[16];
    float* out = (float*)d_out;

    cudaFuncSetAttribute(fused_k, cudaFuncAttributeMaxDynamicSharedMemorySize, SMEM_TOTAL);

    wprep_k<<<dim3(16, 8, 6), dim3(32, 8)>>>(Wr, Wu, Wc, W0, W1, action, observation);
    fused_k<<<256, 512, SMEM_TOTAL>>>(particles, br, bu, bc, b0, b1, W2);
    stage_weights_k<<<BB, NN>>>(weights, uin, b2, out);
    gather_belief_k<<<dim3(128, BB), 256>>>(out);
    belief_reduce_k<<<BB, 64>>>(out);
}

// round 17
// speedup vs baseline: 1.0899x; 1.0899x over previous
#include <cuda_runtime.h>
#include <cuda_fp16.h>
#include <cstdint>
#include <math.h>

#define BB 32
#define NN 1024
#define HH 256
#define AA 32
#define OO 256
#define MM (BB*NN)   // 32768 particle rows

// ---------------- scratch (static device arrays; no allocation) -------------
__device__ float g_NXT[MM*HH];         // pre-permute snapshot (resample-active only)
__device__ float g_ll[MM];
__device__ int   g_idx[MM];
__device__ int   g_should[BB];
__device__ float g_partial[BB*128*HH];

__device__ __align__(128) __half g_U16[MM*HH];
__device__ __align__(128) __half g_ACT[BB*AA];
__device__ __align__(128) __half g_OBS[BB*OO];

// transposed fp16 weights [n][k]: Wr | Wu | Wc | W0 | W1
#define WT_TOTAL 417792
__device__ __align__(128) __half g_WT[WT_TOTAL];
// offsets: Wr 0, Wu 73728, Wc 147456, W0 221184, W1 352256

__device__ __forceinline__ float fast_sigmoid(float x){
    return __fdividef(1.f, 1.f + __expf(-x));
}
__device__ __forceinline__ float fast_tanh(float x){
    float r; asm("tanh.approx.f32 %0, %1;" : "=f"(r) : "f"(x)); return r;
}
__device__ __forceinline__ float gelu_f(float x){ return 0.5f*x*(1.0f+erff(x*0.70710678118654752f)); }
__device__ __forceinline__ float gelu_fast(float x){
    const float c = 0.7978845608028654f;
    return 0.5f*x*(1.0f + fast_tanh(c*(x + 0.044715f*x*x*x)));
}

__device__ __forceinline__ uint32_t packh(float x, float y){
    __half hx = __float2half_rn(x), hy = __float2half_rn(y);
    return (uint32_t)__half_as_ushort(hx) | ((uint32_t)__half_as_ushort(hy) << 16);
}
__device__ __forceinline__ float2 unpackh(uint32_t v){
    __half lo = __ushort_as_half((unsigned short)(v & 0xffff));
    __half hi = __ushort_as_half((unsigned short)(v >> 16));
    return make_float2(__half2float(lo), __half2float(hi));
}

__device__ __forceinline__ void mma16816(float* c, const uint32_t* a, uint32_t b0, uint32_t b1){
    asm volatile("mma.sync.aligned.m16n8k16.row.col.f32.f16.f16.f32 "
        "{%0,%1,%2,%3}, {%4,%5,%6,%7}, {%8,%9}, {%0,%1,%2,%3};"
        : "+f"(c[0]), "+f"(c[1]), "+f"(c[2]), "+f"(c[3])
        : "r"(a[0]), "r"(a[1]), "r"(a[2]), "r"(a[3]), "r"(b0), "r"(b1));
}
__device__ __forceinline__ uint32_t smem_u32(const void* p){
    uint32_t a;
    asm("{ .reg .u64 t; cvta.to.shared.u64 t, %1; cvt.u32.u64 %0, t; }" : "=r"(a) : "l"(p));
    return a;
}

#define CP16(dst, src) \
    asm volatile("cp.async.cg.shared.global [%0], [%1], 16;" :: "r"(dst), "l"(src) : "memory")
#define CP_COMMIT() asm volatile("cp.async.commit_group;" ::: "memory")
#define CP_WAIT1()  asm volatile("cp.async.wait_group 1;" ::: "memory")
#define CP_WAIT0()  asm volatile("cp.async.wait_group 0;" ::: "memory")
#define LDM4(r0,r1,r2,r3,addr) \
    asm volatile("ldmatrix.sync.aligned.m8n8.x4.shared.b16 {%0,%1,%2,%3}, [%4];" \
        : "=r"(r0),"=r"(r1),"=r"(r2),"=r"(r3) : "r"(addr))

// smem layout (R15 proven)
#define PITCH_A 528
#define WPITCH 80
#define WPANEL (256*WPITCH)
#define OFF_A   0
#define OFF_X   67584
#define OFF_W   135168       // 3-stage ring
#define OFF_ACT 196608
#define OFF_OBS 196672
#define OFF_RED 197184
#define SMEM_TOTAL 199232

// ---------------------------------------------------------------------------
// Prep: weights transpose+convert (z=0..4) and act/obs convert (z=5)
// ---------------------------------------------------------------------------
__global__ void wprep_k(const float* __restrict__ Wr, const float* __restrict__ Wu,
                        const float* __restrict__ Wc, const float* __restrict__ W0,
                        const float* __restrict__ W1,
                        const float* __restrict__ act, const float* __restrict__ obs)
{
    const int mid = blockIdx.z;
    const int tx = threadIdx.x, ty = threadIdx.y;
    if (mid == 5){
        if (blockIdx.x == 0 && blockIdx.y == 0){
            const int t = ty*32 + tx;
            for (int i = t; i < BB*AA; i += 256)
                g_ACT[i] = __float2half_rn(act[i]);
            for (int i = t; i < BB*OO; i += 256)
                g_OBS[i] = __float2half_rn(obs[i]);
        }
        return;
    }
    const int Ks[5] = {288,288,288,512,256};
    const size_t offs[5] = {0,73728,147456,221184,352256};
    const float* src = (mid==0)?Wr:(mid==1)?Wu:(mid==2)?Wc:(mid==3)?W0:W1;
    const int K = Ks[mid];
    const int k0 = blockIdx.x * 32;
    if (k0 >= K) return;
    const int n0 = blockIdx.y * 32;

    __shared__ float tile[32][33];
#pragma unroll
    for (int i=0;i<4;i++)
        tile[ty*4+i][tx] = src[(size_t)(k0+ty*4+i)*HH + n0 + tx];
    __syncthreads();
#pragma unroll
    for (int i=0;i<4;i++){
        const int r = ty*4+i;
        g_WT[offs[mid] + (size_t)(n0+r)*K + k0 + tx] = __float2half_rn(tile[tx][r]);
    }
}

// ---------------------------------------------------------------------------
__device__ __forceinline__ void stage_w(uint32_t buf, const __half* __restrict__ w,
                                        int KP, int k0, int tid)
{
#pragma unroll
    for (int i=0;i<2;i++){
        const int idx = tid + i*512;
        const int row = idx >> 2, seg = idx & 3;
        CP16(buf + (uint32_t)(row*WPITCH + seg*16), w + (size_t)row*KP + k0 + seg*8);
    }
}

template<int Kc>
__device__ __forceinline__ void gemm_phase(
    uint32_t aBase, uint32_t bcBase, uint32_t wring,
    const __half* __restrict__ w, int KP,
    int tid, int warpM, int warpN, int t8, int r8,
    float acc[2][8][4], int base)
{
    constexpr int P = Kc / 32;
#pragma unroll
    for (int i=0;i<2;i++)
#pragma unroll
        for (int j=0;j<8;j++)
#pragma unroll
            for (int q=0;q<4;q++) acc[i][j][q] = 0.f;

#pragma unroll 1
    for (int p = 0; p < P; ++p){
        if (p + 1 < P) { CP_WAIT1(); } else { CP_WAIT0(); }
        __syncthreads();

        if (p + 2 < P){
            stage_w(wring + ((base + p + 2) % 3)*WPANEL, w, KP, (p+2)*32, tid);
            CP_COMMIT();
        }

        const uint32_t bS = wring + ((base + p) % 3)*WPANEL;

        uint32_t ahA[2][2][4];
#pragma unroll
        for (int ks = 0; ks < 2; ++ks){
            const int kk = p*32 + ks*16;
            if (kk < 256){
#pragma unroll
                for (int mf = 0; mf < 2; ++mf){
                    const uint32_t off = (uint32_t)((warpM*32 + mf*16 + (t8&1)*8 + r8)*PITCH_A
                                                    + (t8>>1)*16 + kk*2);
                    LDM4(ahA[ks][mf][0],ahA[ks][mf][1],ahA[ks][mf][2],ahA[ks][mf][3], aBase + off);
                }
            } else {
                const uint32_t off = bcBase + (uint32_t)((kk-256)*2 + (t8>>1)*16);
                LDM4(ahA[ks][0][0],ahA[ks][0][1],ahA[ks][0][2],ahA[ks][0][3], off);
                ahA[ks][1][0]=ahA[ks][0][0]; ahA[ks][1][1]=ahA[ks][0][1];
                ahA[ks][1][2]=ahA[ks][0][2]; ahA[ks][1][3]=ahA[ks][0][3];
            }
        }

#pragma unroll
        for (int ks = 0; ks < 2; ++ks){
#pragma unroll
            for (int q = 0; q < 4; ++q){
                const uint32_t boff = (uint32_t)((warpN*64 + q*16 + (t8>>1)*8 + r8)*WPITCH
                                                 + (t8&1)*16 + ks*32);
                uint32_t b0_,b1_,b2_,b3_;
                LDM4(b0_,b1_,b2_,b3_, bS + boff);
                mma16816(acc[0][2*q],   ahA[ks][0], b0_, b1_);
                mma16816(acc[1][2*q],   ahA[ks][1], b0_, b1_);
                mma16816(acc[0][2*q+1], ahA[ks][0], b2_, b3_);
                mma16816(acc[1][2*q+1], ahA[ks][1], b2_, b3_);
            }
        }
    }
}

__device__ __forceinline__ void prestage2(uint32_t wring, const __half* __restrict__ w,
                                          int KP, int base, int tid)
{
    stage_w(wring + (base % 3)*WPANEL,       w, KP, 0,  tid); CP_COMMIT();
    stage_w(wring + ((base + 1) % 3)*WPANEL, w, KP, 32, tid); CP_COMMIT();
}

// ---------------------------------------------------------------------------
// Fused chain: G1a(Wr->XR) G1b(Wu->U) G2(Wc->nxt->dout) G3(W0->Z1) G4(W1->ll)
// ---------------------------------------------------------------------------
__global__ void __launch_bounds__(512, 1) fused_k(
    const float* __restrict__ particles,
    const float* __restrict__ br, const float* __restrict__ bu,
    const float* __restrict__ bc, const float* __restrict__ b0,
    const float* __restrict__ b1, const float* __restrict__ W2,
    float* __restrict__ dout)
{
    extern __shared__ __align__(128) char smem[];
    const uint32_t sb = smem_u32(smem);

    const int tid  = threadIdx.x;
    const int wid  = tid >> 5;
    const int lane = tid & 31;
    const int g    = lane >> 2;
    const int tig  = lane & 3;
    const int t8   = lane >> 3;
    const int r8   = lane & 7;
    const int warpM = wid >> 2;
    const int warpN = wid & 3;
    const int m0   = blockIdx.x * 128;
    const int bidx = blockIdx.x >> 3;
    float* dnxt = dout + 8192;

    if (tid < 4)  CP16(sb + OFF_ACT + tid*16, g_ACT + bidx*AA + tid*8);
    if (tid < 32) CP16(sb + OFF_OBS + tid*16, g_OBS + bidx*OO + tid*8);
    CP_COMMIT();
    prestage2(sb+OFF_W, g_WT, 288, 0, tid);
#pragma unroll
    for (int i=0;i<8;i++){
        const int idx = tid + i*512;
        const int row = idx >> 5, seg = idx & 31;
        const float4 v0 = *(const float4*)(particles + (size_t)(m0+row)*HH + seg*8);
        const float4 v1 = *(const float4*)(particles + (size_t)(m0+row)*HH + seg*8 + 4);
        uint4 pk;
        pk.x = packh(v0.x, v0.y); pk.y = packh(v0.z, v0.w);
        pk.z = packh(v1.x, v1.y); pk.w = packh(v1.z, v1.w);
        *(uint4*)(smem + OFF_A + row*PITCH_A + seg*16) = pk;
    }
    __syncthreads();

    float acc[2][8][4];
    int base = 0;

    // =============== G1a: reset gate -> XR ===============
    gemm_phase<288>(sb+OFF_A, sb+OFF_ACT, sb+OFF_W, g_WT, 288,
                    tid, warpM, warpN, t8, r8, acc, base);
    __syncthreads();
    prestage2(sb+OFF_W, g_WT+73728, 288, base, tid);
#pragma unroll
    for (int mf=0; mf<2; ++mf){
#pragma unroll
        for (int nf=0; nf<8; ++nf){
            const int nc = warpN*64 + nf*8 + tig*2;
            const int m1_ = warpM*32 + mf*16 + g;
            const int m2_ = m1_ + 8;
            const float2 bv = *(const float2*)(br + nc);
            float* c = acc[mf][nf];
            const float2 p1 = unpackh(*(uint32_t*)(smem + OFF_A + m1_*PITCH_A + nc*2));
            const float2 p2 = unpackh(*(uint32_t*)(smem + OFF_A + m2_*PITCH_A + nc*2));
            *(uint32_t*)(smem + OFF_X + m1_*PITCH_A + nc*2) =
                packh(p1.x*fast_sigmoid(c[0]+bv.x), p1.y*fast_sigmoid(c[1]+bv.y));
            *(uint32_t*)(smem + OFF_X + m2_*PITCH_A + nc*2) =
                packh(p2.x*fast_sigmoid(c[2]+bv.x), p2.y*fast_sigmoid(c[3]+bv.y));
        }
    }
    __syncthreads();

    // =============== G1b: update gate -> g_U16 ===============
    gemm_phase<288>(sb+OFF_A, sb+OFF_ACT, sb+OFF_W, g_WT+73728, 288,
                    tid, warpM, warpN, t8, r8, acc, base);
    __syncthreads();
    prestage2(sb+OFF_W, g_WT+147456, 288, base, tid);
#pragma unroll
    for (int mf=0; mf<2; ++mf){
#pragma unroll
        for (int nf=0; nf<8; ++nf){
            const int nc = warpN*64 + nf*8 + tig*2;
            const int m1_ = m0 + warpM*32 + mf*16 + g;
            const int m2_ = m1_ + 8;
            const float2 bv = *(const float2*)(bu + nc);
            float* c = acc[mf][nf];
            *(uint32_t*)&g_U16[(size_t)m1_*HH+nc] = packh(fast_sigmoid(c[0]+bv.x), fast_sigmoid(c[1]+bv.y));
            *(uint32_t*)&g_U16[(size_t)m2_*HH+nc] = packh(fast_sigmoid(c[2]+bv.x), fast_sigmoid(c[3]+bv.y));
        }
    }
    __syncthreads();

    // =============== G2: candidate + GRU combine -> nxt (to dout) ===============
    gemm_phase<288>(sb+OFF_X, sb+OFF_ACT, sb+OFF_W, g_WT+147456, 288,
                    tid, warpM, warpN, t8, r8, acc, base);
    __syncthreads();
    prestage2(sb+OFF_W, g_WT+221184, 512, base, tid);
#pragma unroll
    for (int mf=0; mf<2; ++mf){
#pragma unroll
        for (int nf=0; nf<8; ++nf){
            const int nc = warpN*64 + nf*8 + tig*2;
            const int mm1 = warpM*32 + mf*16 + g;
            const int mm2 = mm1 + 8;
            const int m1_ = m0 + mm1, m2_ = m0 + mm2;
            const float2 bv = *(const float2*)(bc + nc);
            float* c = acc[mf][nf];
            const float2 u1 = unpackh(*(uint32_t*)&g_U16[(size_t)m1_*HH+nc]);
            const float2 u2 = unpackh(*(uint32_t*)&g_U16[(size_t)m2_*HH+nc]);
            const float2 p1 = *(const float2*)(particles + (size_t)m1_*HH + nc);
            const float2 p2 = *(const float2*)(particles + (size_t)m2_*HH + nc);
            float2 r1, r2;
            r1.x = (1.f-u1.x)*p1.x + u1.x*fast_tanh(c[0]+bv.x);
            r1.y = (1.f-u1.y)*p1.y + u1.y*fast_tanh(c[1]+bv.y);
            r2.x = (1.f-u2.x)*p2.x + u2.x*fast_tanh(c[2]+bv.x);
            r2.y = (1.f-u2.y)*p2.y + u2.y*fast_tanh(c[3]+bv.y);
            *(float2*)(dnxt + (size_t)m1_*HH + nc) = r1;
            *(float2*)(dnxt + (size_t)m2_*HH + nc) = r2;
            *(uint32_t*)(smem + OFF_A + mm1*PITCH_A + nc*2) = packh(r1.x, r1.y);
            *(uint32_t*)(smem + OFF_A + mm2*PITCH_A + nc*2) = packh(r2.x, r2.y);
        }
    }
    __syncthreads();

    // =============== G3: MLP layer 0 -> Z1 (fast gelu) ===============
    gemm_phase<512>(sb+OFF_A, sb+OFF_OBS, sb+OFF_W, g_WT+221184, 512,
                    tid, warpM, warpN, t8, r8, acc, base);
    __syncthreads();
    prestage2(sb+OFF_W, g_WT+352256, 256, base, tid);
#pragma unroll
    for (int mf=0; mf<2; ++mf){
#pragma unroll
        for (int nf=0; nf<8; ++nf){
            const int nc = warpN*64 + nf*8 + tig*2;
            const int mm1 = warpM*32 + mf*16 + g;
            const int mm2 = mm1 + 8;
            const float2 bv = *(const float2*)(b0 + nc);
            float* c = acc[mf][nf];
            *(uint32_t*)(smem + OFF_X + mm1*PITCH_A + nc*2) =
                packh(gelu_fast(c[0]+bv.x), gelu_fast(c[1]+bv.y));
            *(uint32_t*)(smem + OFF_X + mm2*PITCH_A + nc*2) =
                packh(gelu_fast(c[2]+bv.x), gelu_fast(c[3]+bv.y));
        }
    }
    __syncthreads();

    // =============== G4: MLP layer 1 + W2 dot -> log_lik (exact gelu) ===============
    gemm_phase<256>(sb+OFF_X, sb+OFF_OBS, sb+OFF_W, g_WT+352256, 256,
                    tid, warpM, warpN, t8, r8, acc, base);
    {
        float* red = (float*)(smem + OFF_RED);
        float pr[2][2] = {{0.f,0.f},{0.f,0.f}};
#pragma unroll
        for (int mf=0; mf<2; ++mf){
#pragma unroll
            for (int nf=0; nf<8; ++nf){
                const int nc = warpN*64 + nf*8 + tig*2;
                const float2 bv = *(const float2*)(b1 + nc);
                const float2 wv = *(const float2*)(W2 + nc);
                float* c = acc[mf][nf];
                pr[mf][0] += gelu_f(c[0]+bv.x)*wv.x + gelu_f(c[1]+bv.y)*wv.y;
                pr[mf][1] += gelu_f(c[2]+bv.x)*wv.x + gelu_f(c[3]+bv.y)*wv.y;
            }
        }
        __syncthreads();
#pragma unroll
        for (int mf=0; mf<2; ++mf)
#pragma unroll
            for (int rr=0; rr<2; ++rr){
                float v = pr[mf][rr];
                v += __shfl_xor_sync(0xffffffffu, v, 1);
                v += __shfl_xor_sync(0xffffffffu, v, 2);
                if (tig == 0) red[(warpM*32 + mf*16 + rr*8 + g)*4 + warpN] = v;
            }
        __syncthreads();
        if (tid < 128)
            g_ll[m0 + tid] = red[tid*4] + red[tid*4+1] + red[tid*4+2] + red[tid*4+3];
    }
}

// ---------------------------------------------------------------------------
// Per-batch weight update (shuffle-based); also writes g_should.
// ---------------------------------------------------------------------------
__global__ void __launch_bounds__(NN) stage_weights_k(
    const float* __restrict__ weights,
    const float* __restrict__ uin,
    const float* __restrict__ b2,
    float* __restrict__ dout)
{
    __shared__ float sh[NN];
    __shared__ float swarp[32];
    __shared__ float sbc;
    const int b = blockIdx.x;
    const int n = threadIdx.x;
    const int m = b*NN + n;
    const int w = n >> 5, l = n & 31;

    const float ll = g_ll[m] + b2[0];
    const float lw = __logf(weights[m] + 1e-10f) + ll;

    float v = lw;
#pragma unroll
    for (int o=16;o>0;o>>=1) v = fmaxf(v, __shfl_xor_sync(0xffffffffu, v, o));
    if (l==0) swarp[w] = v;
    __syncthreads();
    if (w==0){
        float x = swarp[l];
#pragma unroll
        for (int o=16;o>0;o>>=1) x = fmaxf(x, __shfl_xor_sync(0xffffffffu, x, o));
        if (l==0) sbc = x;
    }
    __syncthreads();
    const float mx = sbc;
    __syncthreads();

    const float e = __expf(lw - mx);
    v = e;
#pragma unroll
    for (int o=16;o>0;o>>=1) v += __shfl_xor_sync(0xffffffffu, v, o);
    if (l==0) swarp[w] = v;
    __syncthreads();
    if (w==0){
        float x = swarp[l];
#pragma unroll
        for (int o=16;o>0;o>>=1) x += __shfl_xor_sync(0xffffffffu, x, o);
        if (l==0) sbc = x;
    }
    __syncthreads();
    const float S = sbc;
    __syncthreads();
    const float nw = __fdividef(e, S);

    v = nw*nw;
#pragma unroll
    for (int o=16;o>0;o>>=1) v += __shfl_xor_sync(0xffffffffu, v, o);
    if (l==0) swarp[w] = v;
    __syncthreads();
    if (w==0){
        float x = swarp[l];
#pragma unroll
        for (int o=16;o>0;o>>=1) x += __shfl_xor_sync(0xffffffffu, x, o);
        if (l==0) sbc = x;
    }
    __syncthreads();
    const float ess = __fdividef(1.0f, sbc + 1e-10f);
    __syncthreads();
    const bool should = ess < 0.5f * (float)NN;

    float sc = nw;
#pragma unroll
    for (int o=1;o<32;o<<=1){
        float t = __shfl_up_sync(0xffffffffu, sc, o);
        if (l >= o) sc += t;
    }
    if (l==31) swarp[w] = sc;
    __syncthreads();
    if (w==0){
        float t = swarp[l];
        float ts = t;
#pragma unroll
        for (int o=1;o<32;o<<=1){
            float u2 = __shfl_up_sync(0xffffffffu, ts, o);
            if (l >= o) ts += u2;
        }
        swarp[l] = ts - t;
    }
    __syncthreads();
    sc += swarp[w];
    sh[n] = sc;
    __syncthreads();

    float pos = uin[b]*(1.0f/(float)NN) + (float)n*(1.0f/(float)NN);
    pos = fminf(pos, 0.9999f);
    int lo = 0, hi = NN;
    while (lo < hi) {
        int mid = (lo + hi) >> 1;
        if (sh[mid] < pos) lo = mid + 1; else hi = mid;
    }
    int idx = lo < (NN-1) ? lo : (NN-1);

    g_idx[m] = should ? idx : n;
    const float wf = should ? (1.0f/(float)NN) : nw;
    dout[8192 + (size_t)MM*HH + m] = wf;
    if (n == 0){
        dout[8192 + (size_t)MM*HH + MM + b] = ess;
        g_should[b] = should ? 1 : 0;
    }
}

// ---------------------------------------------------------------------------
// Snapshot dout nxt rows -> g_NXT for resample-active batches only.
// ---------------------------------------------------------------------------
__global__ void __launch_bounds__(256) resample_copy_k(const float* __restrict__ dout)
{
    const int b = blockIdx.y;
    if (!g_should[b]) return;
    const int chunk = blockIdx.x;
    const int h4  = (threadIdx.x & 63) * 4;
    const int rg  = threadIdx.x >> 6;
    const float* dnxt = dout + 8192;
#pragma unroll
    for (int r=0; r<2; r++) {
        const int j = chunk*8 + rg*2 + r;
        *(float4*)(g_NXT + (size_t)(b*NN + j)*HH + h4) =
            *(const float4*)(dnxt + (size_t)(b*NN + j)*HH + h4);
    }
}

// ---------------------------------------------------------------------------
// Gather (permute only if should) + belief partial.
// ---------------------------------------------------------------------------
__global__ void __launch_bounds__(256) gather_belief_k(float* __restrict__ dout)
{
    __shared__ float4 sbuf[256];
    const int b = blockIdx.y;
    const bool should = g_should[b] != 0;
    const int chunk = blockIdx.x;
    const int h4  = (threadIdx.x & 63) * 4;
    const int rg  = threadIdx.x >> 6;
    const float* dw = dout + 8192 + (size_t)MM*HH;
    float* dnxt = dout + 8192;

    float4 acc = make_float4(0.f,0.f,0.f,0.f);
#pragma unroll
    for (int r=0; r<2; r++) {
        const int j = chunk*8 + rg*2 + r;
        const float wj = dw[b*NN + j];
        float4 v;
        if (should){
            const int src = g_idx[b*NN + j];
            v = *(const float4*)(g_NXT + (size_t)(b*NN + src)*HH + h4);
            *(float4*)(dnxt + (size_t)(b*NN + j)*HH + h4) = v;
        } else {
            v = *(const float4*)(dnxt + (size_t)(b*NN + j)*HH + h4);
        }
        acc.x = fmaf(v.x, wj, acc.x);
        acc.y = fmaf(v.y, wj, acc.y);
        acc.z = fmaf(v.z, wj, acc.z);
        acc.w = fmaf(v.w, wj, acc.w);
    }
    sbuf[threadIdx.x] = acc;
    __syncthreads();
    if (threadIdx.x < 64){
        float4 a0 = sbuf[threadIdx.x];
        float4 a1 = sbuf[threadIdx.x + 64];
        float4 a2 = sbuf[threadIdx.x + 128];
        float4 a3 = sbuf[threadIdx.x + 192];
        float4 s;
        s.x = (a0.x + a1.x) + (a2.x + a3.x);
        s.y = (a0.y + a1.y) + (a2.y + a3.y);
        s.z = (a0.z + a1.z) + (a2.z + a3.z);
        s.w = (a0.w + a1.w) + (a2.w + a3.w);
        *(float4*)(g_partial + (size_t)(b*128 + chunk)*HH + h4) = s;
    }
}

__global__ void __launch_bounds__(256) belief_reduce_k(float* __restrict__ dout)
{
    __shared__ float4 sred[256];
    const int b = blockIdx.x;
    const int h4 = (threadIdx.x & 63) * 4;
    const int part = threadIdx.x >> 6;
    float4 s = make_float4(0.f,0.f,0.f,0.f);
    for (int c = part*32; c < part*32 + 32; c++){
        const float4 v = *(const float4*)(g_partial + (size_t)(b*128 + c)*HH + h4);
        s.x += v.x; s.y += v.y; s.z += v.z; s.w += v.w;
    }
    sred[threadIdx.x] = s;
    __syncthreads();
    if (threadIdx.x < 64){
        float4 a0 = sred[threadIdx.x];
        float4 a1 = sred[threadIdx.x + 64];
        float4 a2 = sred[threadIdx.x + 128];
        float4 a3 = sred[threadIdx.x + 192];
        float4 o;
        o.x = (a0.x + a1.x) + (a2.x + a3.x);
        o.y = (a0.y + a1.y) + (a2.y + a3.y);
        o.z = (a0.z + a1.z) + (a2.z + a3.z);
        o.w = (a0.w + a1.w) + (a2.w + a3.w);
        *(float4*)(dout + b*HH + h4) = o;
    }
}

// ---------------------------------------------------------------------------
extern "C" void kernel_launch(void* const* d_in, const int* in_sizes, int n_in,
                              void* d_out, int out_size)
{
    (void)in_sizes; (void)n_in; (void)out_size;
    const float* particles   = (const float*)d_in[0];
    const float* weights     = (const float*)d_in[1];
    const float* action      = (const float*)d_in[2];
    const float* observation = (const float*)d_in[3];
    const float* uin         = (const float*)d_in[4];
    const float* Wr = (const float*)d_in[5];  const float* br = (const float*)d_in[6];
    const float* Wu = (const float*)d_in[7];  const float* bu = (const float*)d_in[8];
    const float* Wc = (const float*)d_in[9];  const float* bc = (const float*)d_in[10];
    const float* W0 = (const float*)d_in[11]; const float* b0 = (const float*)d_in[12];
    const float* W1 = (const float*)d_in[13]; const float* b1 = (const float*)d_in[14];
    const float* W2 = (const float*)d_in[15]; const float* b2 = (const float*)d_in[16];
    float* out = (float*)d_out;

    cudaFuncSetAttribute(fused_k, cudaFuncAttributeMaxDynamicSharedMemorySize, SMEM_TOTAL);

    wprep_k<<<dim3(16, 8, 6), dim3(32, 8)>>>(Wr, Wu, Wc, W0, W1, action, observation);
    fused_k<<<256, 512, SMEM_TOTAL>>>(particles, br, bu, bc, b0, b1, W2, out);
    stage_weights_k<<<BB, NN>>>(weights, uin, b2, out);
    resample_copy_k<<<dim3(128, BB), 256>>>(out);
    gather_belief_k<<<dim3(128, BB), 256>>>(out);
    belief_reduce_k<<<BB, 256>>>(out);
}